// round 1
// baseline (speedup 1.0000x reference)
#include <cuda_runtime.h>
#include <math.h>

// ---------------- scratch (device globals — no allocations allowed) --------
__device__ float g_mixed[8192];   // raw qkv GEMV output (pre-conv, pre-silu)
__device__ float g_z[4096];
__device__ float g_beta[32];      // raw (pre-sigmoid)
__device__ float g_a[32];         // raw (pre softplus add)
__device__ float g_outflat[4096]; // gated+rmsnormed per-head output

// out layout in d_out: [0,2048) final out | [2048, 2048+524288) new_state |
//                      [2048+524288, +24576) new_conv
#define OFF_STATE 2048
#define OFF_CONV  (2048 + 524288)

// ---------------- K1: fused GEMV (12352 rows x 2048) -----------------------
// rows 0..8191    -> W_qkv  -> g_mixed (+ new_conv emit)
// rows 8192..12287-> W_z    -> g_z
// rows 12288..12319-> W_b   -> g_beta
// rows 12320..12351-> W_a   -> g_a
__global__ __launch_bounds__(256) void k_gemv_in(
    const float* __restrict__ x,
    const float* __restrict__ W_qkv,
    const float* __restrict__ W_z,
    const float* __restrict__ W_b,
    const float* __restrict__ W_a,
    const float* __restrict__ conv_state,
    float* __restrict__ out)
{
    __shared__ float sx[2048];
    int tid = threadIdx.x;
    // stage x (8 KB) into shared
    for (int i = tid; i < 512; i += 256)
        ((float4*)sx)[i] = ((const float4*)x)[i];
    __syncthreads();

    int warp = tid >> 5;
    int lane = tid & 31;
    int row = blockIdx.x * 8 + warp;           // grid = 1544 -> exactly 12352 rows

    const float* wrow;
    if (row < 8192)        wrow = W_qkv + (size_t)row * 2048;
    else if (row < 12288)  wrow = W_z   + (size_t)(row - 8192) * 2048;
    else if (row < 12320)  wrow = W_b   + (size_t)(row - 12288) * 2048;
    else                   wrow = W_a   + (size_t)(row - 12320) * 2048;

    const float4* w4 = (const float4*)wrow;
    const float4* x4 = (const float4*)sx;
    float acc = 0.f;
    #pragma unroll
    for (int i = 0; i < 16; i++) {
        float4 w = w4[i * 32 + lane];
        float4 v = x4[i * 32 + lane];
        acc += w.x * v.x + w.y * v.y + w.z * v.z + w.w * v.w;
    }
    #pragma unroll
    for (int o = 16; o; o >>= 1) acc += __shfl_down_sync(0xffffffffu, acc, o);

    if (lane == 0) {
        if (row < 8192) {
            g_mixed[row] = acc;
            // new_conv[c] = { conv_state[c][1], conv_state[c][2], mixed[c] }
            float* nc = out + OFF_CONV + (size_t)row * 3;
            nc[0] = conv_state[row * 3 + 1];
            nc[1] = conv_state[row * 3 + 2];
            nc[2] = acc;
        } else if (row < 12288) {
            g_z[row - 8192] = acc;
        } else if (row < 12320) {
            g_beta[row - 12288] = acc;
        } else {
            g_a[row - 12320] = acc;
        }
    }
}

// ---------------- helpers ---------------------------------------------------
__device__ __forceinline__ float silu_f(float v) {
    return v / (1.f + expf(-v));
}
__device__ __forceinline__ float softplus_f(float v) {
    return (v > 20.f) ? v : log1pf(expf(v));
}

// block (128 threads) sum reduction
__device__ __forceinline__ float blockSum128(float v, float* red) {
    #pragma unroll
    for (int o = 16; o; o >>= 1) v += __shfl_down_sync(0xffffffffu, v, o);
    int w = threadIdx.x >> 5;
    if ((threadIdx.x & 31) == 0) red[w] = v;
    __syncthreads();
    float r = red[0] + red[1] + red[2] + red[3];
    __syncthreads();
    return r;
}

// depthwise conv (window 4) + silu for one channel
__device__ __forceinline__ float conv_silu(
    int c, const float* __restrict__ cs, const float* __restrict__ cw)
{
    float v = cs[c * 3 + 0] * cw[c * 4 + 0]
            + cs[c * 3 + 1] * cw[c * 4 + 1]
            + cs[c * 3 + 2] * cw[c * 4 + 2]
            + g_mixed[c]    * cw[c * 4 + 3];
    return silu_f(v);
}

// ---------------- K2: per-head delta rule + state update + gating ----------
// grid = 32 (one block per head), block = 128 (one thread per v-column)
__global__ __launch_bounds__(128) void k_head(
    const float* __restrict__ state,
    const float* __restrict__ conv_state,
    const float* __restrict__ conv_w,
    const float* __restrict__ A_log,
    const float* __restrict__ dt_bias,
    const float* __restrict__ norm_w,
    float* __restrict__ out)
{
    int h = blockIdx.x;
    int j = threadIdx.x;
    __shared__ float sq[128], sk[128], red[4];

    int grp = h >> 1;                 // q/k repeat(2) over 16 groups
    float qraw = conv_silu(grp * 128 + j,        conv_state, conv_w);
    float kraw = conv_silu(2048 + grp * 128 + j, conv_state, conv_w);
    float vval = conv_silu(4096 + h * 128 + j,   conv_state, conv_w);

    float q2 = blockSum128(qraw * qraw, red);
    float k2 = blockSum128(kraw * kraw, red);
    const float inv_sqrt128 = 0.08838834764831845f;  // 1/sqrt(128)
    float qj = qraw * rsqrtf(q2 + 1e-6f) * inv_sqrt128;
    float kj = kraw * rsqrtf(k2 + 1e-6f);
    sq[j] = qj; sk[j] = kj;
    float qk = blockSum128(qj * kj, red);   // also syncs -> sq/sk visible

    float g    = expf(-expf(A_log[h]) * softplus_f(g_a[h] + dt_bias[h]));
    float beta = 1.f / (1.f + expf(-g_beta[h]));

    const float* S = state + (size_t)h * 16384;
    float kv = 0.f, sqv = 0.f;
    #pragma unroll 8
    for (int kk = 0; kk < 128; kk++) {
        float s = S[kk * 128 + j] * g;   // coalesced across j
        kv  += s * sk[kk];
        sqv += s * sq[kk];
    }
    float delta = (vval - kv) * beta;

    float* NS = out + OFF_STATE + (size_t)h * 16384;
    #pragma unroll 8
    for (int kk = 0; kk < 128; kk++) {
        NS[kk * 128 + j] = S[kk * 128 + j] * g + sk[kk] * delta;  // L2 hit on S
    }

    // out[v] = sum_k (s + k*delta)*q = sqv + delta * (k.q)
    float o = sqv + delta * qk;
    float zz = g_z[h * 128 + j];
    float gated = o * silu_f(zz);
    float m = blockSum128(gated * gated, red) * (1.f / 128.f);
    g_outflat[h * 128 + j] = gated * rsqrtf(m + 1e-6f) * norm_w[j];
}

// ---------------- K3: output GEMV (2048 rows x 4096) -----------------------
__global__ __launch_bounds__(256) void k_gemv_out(
    const float* __restrict__ W_out, float* __restrict__ out)
{
    __shared__ float so[4096];
    int tid = threadIdx.x;
    for (int i = tid; i < 1024; i += 256)
        ((float4*)so)[i] = ((const float4*)g_outflat)[i];
    __syncthreads();

    int row = blockIdx.x * 8 + (tid >> 5);   // grid = 256 -> 2048 rows
    int lane = tid & 31;
    const float4* w4 = (const float4*)(W_out + (size_t)row * 4096);
    const float4* x4 = (const float4*)so;
    float acc = 0.f;
    #pragma unroll
    for (int i = 0; i < 32; i++) {
        float4 w = w4[i * 32 + lane];
        float4 v = x4[i * 32 + lane];
        acc += w.x * v.x + w.y * v.y + w.z * v.z + w.w * v.w;
    }
    #pragma unroll
    for (int o = 16; o; o >>= 1) acc += __shfl_down_sync(0xffffffffu, acc, o);
    if (lane == 0) out[row] = acc;
}

// ---------------- launcher --------------------------------------------------
extern "C" void kernel_launch(void* const* d_in, const int* in_sizes, int n_in,
                              void* d_out, int out_size)
{
    const float* x          = (const float*)d_in[0];
    const float* state      = (const float*)d_in[1];
    const float* conv_state = (const float*)d_in[2];
    const float* W_qkv      = (const float*)d_in[3];
    const float* W_z        = (const float*)d_in[4];
    const float* W_b        = (const float*)d_in[5];
    const float* W_a        = (const float*)d_in[6];
    const float* conv_w     = (const float*)d_in[7];
    const float* A_log      = (const float*)d_in[8];
    const float* dt_bias    = (const float*)d_in[9];
    const float* norm_w     = (const float*)d_in[10];
    const float* W_out      = (const float*)d_in[11];
    float* out = (float*)d_out;

    k_gemv_in<<<1544, 256>>>(x, W_qkv, W_z, W_b, W_a, conv_state, out);
    k_head<<<32, 128>>>(state, conv_state, conv_w, A_log, dt_bias, norm_w, out);
    k_gemv_out<<<256, 256>>>(W_out, out);
}

// round 2
// speedup vs baseline: 1.5440x; 1.5440x over previous
#include <cuda_runtime.h>
#include <math.h>

// ---------------- scratch (device globals) ---------------------------------
__device__ float g_mixed[8192];
__device__ float g_z[4096];
__device__ float g_beta[32];
__device__ float g_a[32];
__device__ float g_outflat[4096];

#define OFF_STATE 2048
#define OFF_CONV  (2048 + 524288)

// ---------------- K1: fused GEMV (12352 rows x 2048) -----------------------
__global__ __launch_bounds__(256, 3) void k_gemv_in(
    const float* __restrict__ x,
    const float* __restrict__ W_qkv,
    const float* __restrict__ W_z,
    const float* __restrict__ W_b,
    const float* __restrict__ W_a,
    const float* __restrict__ conv_state,
    float* __restrict__ out)
{
    __shared__ float sx[2048];
    int tid = threadIdx.x;
    for (int i = tid; i < 512; i += 256)
        ((float4*)sx)[i] = ((const float4*)x)[i];
    __syncthreads();

    int warp = tid >> 5;
    int lane = tid & 31;
    int row = blockIdx.x * 8 + warp;           // grid = 1544 -> 12352 rows

    const float* wrow;
    if (row < 8192)        wrow = W_qkv + (size_t)row * 2048;
    else if (row < 12288)  wrow = W_z   + (size_t)(row - 8192) * 2048;
    else if (row < 12320)  wrow = W_b   + (size_t)(row - 12288) * 2048;
    else                   wrow = W_a   + (size_t)(row - 12320) * 2048;

    const float4* w4 = (const float4*)wrow;
    const float4* x4 = (const float4*)sx;
    float acc0 = 0.f, acc1 = 0.f;
    #pragma unroll
    for (int half = 0; half < 2; half++) {
        float4 wv[8];
        #pragma unroll
        for (int i = 0; i < 8; i++)
            wv[i] = w4[(half * 8 + i) * 32 + lane];
        #pragma unroll
        for (int i = 0; i < 8; i++) {
            float4 v = x4[(half * 8 + i) * 32 + lane];
            acc0 += wv[i].x * v.x + wv[i].y * v.y;
            acc1 += wv[i].z * v.z + wv[i].w * v.w;
        }
    }
    float acc = acc0 + acc1;
    #pragma unroll
    for (int o = 16; o; o >>= 1) acc += __shfl_down_sync(0xffffffffu, acc, o);

    if (lane == 0) {
        if (row < 8192) {
            g_mixed[row] = acc;
            float* nc = out + OFF_CONV + (size_t)row * 3;
            nc[0] = conv_state[row * 3 + 1];
            nc[1] = conv_state[row * 3 + 2];
            nc[2] = acc;
        } else if (row < 12288) {
            g_z[row - 8192] = acc;
        } else if (row < 12320) {
            g_beta[row - 12288] = acc;
        } else {
            g_a[row - 12320] = acc;
        }
    }
}

// ---------------- helpers ---------------------------------------------------
__device__ __forceinline__ float silu_f(float v) { return v / (1.f + expf(-v)); }
__device__ __forceinline__ float softplus_f(float v) {
    return (v > 20.f) ? v : log1pf(expf(v));
}
__device__ __forceinline__ float conv_silu(
    int c, const float* __restrict__ cs, const float* __restrict__ cw)
{
    float v = cs[c * 3 + 0] * cw[c * 4 + 0]
            + cs[c * 3 + 1] * cw[c * 4 + 1]
            + cs[c * 3 + 2] * cw[c * 4 + 2]
            + g_mixed[c]    * cw[c * 4 + 3];
    return silu_f(v);
}

// 512-thread block sum
__device__ __forceinline__ float blockSum512(float v, float* red) {
    #pragma unroll
    for (int o = 16; o; o >>= 1) v += __shfl_down_sync(0xffffffffu, v, o);
    int w = threadIdx.x >> 5;
    if ((threadIdx.x & 31) == 0) red[w] = v;
    __syncthreads();
    float r = 0.f;
    #pragma unroll
    for (int i = 0; i < 16; i++) r += red[i];
    __syncthreads();
    return r;
}

// ---------------- K2: per-head delta rule (32 blocks x 512 threads) --------
__global__ __launch_bounds__(512) void k_head(
    const float* __restrict__ state,
    const float* __restrict__ conv_state,
    const float* __restrict__ conv_w,
    const float* __restrict__ A_log,
    const float* __restrict__ dt_bias,
    const float* __restrict__ norm_w,
    float* __restrict__ out)
{
    int h   = blockIdx.x;
    int tid = threadIdx.x;
    int j   = tid & 127;
    int sl  = tid >> 7;          // 0..3: kk slice
    int base = sl * 32;

    __shared__ float sq[128], sk[128], sv[128], sdelta[128];
    __shared__ float red[16];
    __shared__ float skv[512], ssqv[512];

    if (tid < 128) {
        int grp = h >> 1;
        sq[tid] = conv_silu(grp * 128 + tid,        conv_state, conv_w); // raw q
        sk[tid] = conv_silu(2048 + grp * 128 + tid, conv_state, conv_w); // raw k
        sv[tid] = conv_silu(4096 + h * 128 + tid,   conv_state, conv_w);
    }
    __syncthreads();

    float q2 = blockSum512(tid < 128 ? sq[tid] * sq[tid] : 0.f, red);
    float k2 = blockSum512(tid < 128 ? sk[tid] * sk[tid] : 0.f, red);
    const float inv_sqrt128 = 0.08838834764831845f;
    if (tid < 128) {
        sq[tid] = sq[tid] * rsqrtf(q2 + 1e-6f) * inv_sqrt128;
        sk[tid] = sk[tid] * rsqrtf(k2 + 1e-6f);
    }
    __syncthreads();
    float qk = blockSum512(tid < 128 ? sq[tid] * sk[tid] : 0.f, red);

    float g    = expf(-expf(A_log[h]) * softplus_f(g_a[h] + dt_bias[h]));
    float beta = 1.f / (1.f + expf(-g_beta[h]));

    // main pass: read state once, keep s*g in registers
    const float* S = state + (size_t)h * 16384;
    float sg[32];
    float kv = 0.f, sqv = 0.f;
    #pragma unroll
    for (int r = 0; r < 32; r++) {
        float s = S[(base + r) * 128 + j] * g;
        sg[r] = s;
        kv  += s * sk[base + r];
        sqv += s * sq[base + r];
    }
    skv[tid] = kv; ssqv[tid] = sqv;
    __syncthreads();

    if (tid < 128) {
        float kvt  = skv[j]  + skv[j + 128]  + skv[j + 256]  + skv[j + 384];
        float sqvt = ssqv[j] + ssqv[j + 128] + ssqv[j + 256] + ssqv[j + 384];
        float delta = (sv[j] - kvt) * beta;
        sdelta[j] = delta;
        // out[v] = sqv_total + delta * (k.q)
        sv[j] = sqvt + delta * qk;   // reuse sv as 'o'
    }
    __syncthreads();

    // state write from registers
    float delta_j = sdelta[j];
    float* NS = out + OFF_STATE + (size_t)h * 16384;
    #pragma unroll
    for (int r = 0; r < 32; r++)
        NS[(base + r) * 128 + j] = sg[r] + sk[base + r] * delta_j;

    // gating + rmsnorm
    float gated = 0.f;
    if (tid < 128) {
        float zz = g_z[h * 128 + tid];
        gated = sv[tid] * silu_f(zz);
    }
    float m = blockSum512(tid < 128 ? gated * gated : 0.f, red) * (1.f / 128.f);
    if (tid < 128)
        g_outflat[h * 128 + tid] = gated * rsqrtf(m + 1e-6f) * norm_w[tid];
}

// ---------------- K3: output GEMV (2048 rows x 4096) -----------------------
__global__ __launch_bounds__(256, 3) void k_gemv_out(
    const float* __restrict__ W_out, float* __restrict__ out)
{
    __shared__ float so[4096];
    int tid = threadIdx.x;
    for (int i = tid; i < 1024; i += 256)
        ((float4*)so)[i] = ((const float4*)g_outflat)[i];
    __syncthreads();

    int row  = blockIdx.x * 8 + (tid >> 5);   // grid = 256 -> 2048 rows
    int lane = tid & 31;
    const float4* w4 = (const float4*)(W_out + (size_t)row * 4096);
    const float4* x4 = (const float4*)so;
    float acc0 = 0.f, acc1 = 0.f;
    #pragma unroll
    for (int q = 0; q < 4; q++) {
        float4 wv[8];
        #pragma unroll
        for (int i = 0; i < 8; i++)
            wv[i] = w4[(q * 8 + i) * 32 + lane];
        #pragma unroll
        for (int i = 0; i < 8; i++) {
            float4 v = x4[(q * 8 + i) * 32 + lane];
            acc0 += wv[i].x * v.x + wv[i].y * v.y;
            acc1 += wv[i].z * v.z + wv[i].w * v.w;
        }
    }
    float acc = acc0 + acc1;
    #pragma unroll
    for (int o = 16; o; o >>= 1) acc += __shfl_down_sync(0xffffffffu, acc, o);
    if (lane == 0) out[row] = acc;
}

// ---------------- launcher --------------------------------------------------
extern "C" void kernel_launch(void* const* d_in, const int* in_sizes, int n_in,
                              void* d_out, int out_size)
{
    const float* x          = (const float*)d_in[0];
    const float* state      = (const float*)d_in[1];
    const float* conv_state = (const float*)d_in[2];
    const float* W_qkv      = (const float*)d_in[3];
    const float* W_z        = (const float*)d_in[4];
    const float* W_b        = (const float*)d_in[5];
    const float* W_a        = (const float*)d_in[6];
    const float* conv_w     = (const float*)d_in[7];
    const float* A_log      = (const float*)d_in[8];
    const float* dt_bias    = (const float*)d_in[9];
    const float* norm_w     = (const float*)d_in[10];
    const float* W_out      = (const float*)d_in[11];
    float* out = (float*)d_out;

    k_gemv_in<<<1544, 256>>>(x, W_qkv, W_z, W_b, W_a, conv_state, out);
    k_head<<<32, 512>>>(state, conv_state, conv_w, A_log, dt_bias, norm_w, out);
    k_gemv_out<<<256, 256>>>(W_out, out);
}